// round 8
// baseline (speedup 1.0000x reference)
#include <cuda_runtime.h>
#include <math.h>

// Log-polar patch extraction — 8 warps per batch, warp-autonomous.
//   img:      [B,1,256,256] f32   (d_in[0])
//   kpLoc:    [B,2]         f32   (d_in[1])
//   scaling:  [B]           f32   (d_in[2])
//   rotation: [B]           f32   (d_in[3])
//   out:      [B,1,64,64]   f32
//
// Geometry: kpLoc in [-0.6,0.6], scaling in [0.5,2.0] => pixel-space sample
// radius r128 <= 2.05; all bilinear footprints fall inside the 8x8 window
// [floor(c)-3, floor(c)+4]^2, strictly interior to the 256x256 image.
//
// Each warp owns 8 output rows of one batch (16384 warps total for latency
// hiding). Lane L owns radii j = 2L, 2L+1 (registers). Lane k<8 holds the
// (cos,sin) of the SOURCE angle of output row row0+k (roll folded before
// trig); body broadcasts via shfl. Floor/index use the magic-float trick
// (2^23 - 0.5): all fixed-latency ops, no F2I/FRND chains.

#define RES 64
#define IMG_W 256
#define PI_F 3.14159265358979323846f
#define MAGIC (8388608.0f - 0.5f)     // 2^23 - 0.5 : RNE(p + MAGIC) == 2^23 + floor(p)

__device__ __forceinline__ float2 fma2(float2 a, float2 b, float2 c) {
    float2 d;
    asm("fma.rn.f32x2 %0, %1, %2, %3;"
        : "=l"(reinterpret_cast<unsigned long long&>(d))
        : "l"(reinterpret_cast<unsigned long long&>(a)),
          "l"(reinterpret_cast<unsigned long long&>(b)),
          "l"(reinterpret_cast<unsigned long long&>(c)));
    return d;
}
__device__ __forceinline__ float2 add2(float2 a, float2 b) {
    float2 d;
    asm("add.rn.f32x2 %0, %1, %2;"
        : "=l"(reinterpret_cast<unsigned long long&>(d))
        : "l"(reinterpret_cast<unsigned long long&>(a)),
          "l"(reinterpret_cast<unsigned long long&>(b)));
    return d;
}

__global__ void __launch_bounds__(128)
logpolar_kernel(const float* __restrict__ img,
                const float* __restrict__ kpLoc,
                const float* __restrict__ scaling,
                const float* __restrict__ rotation,
                float* __restrict__ out)
{
    const int wid  = threadIdx.x >> 5;
    const int lane = threadIdx.x & 31;
    const int b    = blockIdx.x >> 1;                    // 2 blocks per batch
    const int row0 = (((blockIdx.x & 1) << 2) | wid) << 3;  // this warp's 8 rows

    __shared__ float s_tile[4][64];   // per-warp 8x8 window, pre-scaled by 1/255

    // Per-batch scalars (same address across warp -> broadcast LDG, L1-hot)
    const float rot = rotation[b];
    const float scl = scaling[b];
    const float kx  = kpLoc[2 * b + 0];
    const float ky  = kpLoc[2 * b + 1];
    const float maxR = 6.0f * scl;

    // Sample-grid center in pixel coords; 8x8 window origin
    const float cx = kx * 128.0f + 127.5f;
    const float cy = ky * 128.0f + 127.5f;
    const float fx0 = floorf(cx);
    const float fy0 = floorf(cy);
    const int   x0  = (int)fx0 - 3;
    const int   y0  = (int)fy0 - 3;
    const float cxr = (cx - fx0) + 3.0f;   // window-relative center, in [3,4)
    const float cyr = (cy - fy0) + 3.0f;

    // ---- tile loads first (latency overlapped by MUFU work below) ----
    const float* __restrict__ im = img + (size_t)b * (IMG_W * IMG_W);
    float p0 = __ldg(im + (y0 + (lane >> 3)) * IMG_W + x0 + (lane & 7));
    float p1 = __ldg(im + (y0 + 4 + (lane >> 3)) * IMG_W + x0 + (lane & 7));

    // ---- roll amount (banker's rounding to match jnp.round) ----
    int n = (int)rintf(rot * 57.29577951308232f * (1.0f / 5.625f));
    n = ((n % RES) + RES) % RES;

    // ---- lane k (k=lane&7) holds (cos,sin) of source angle of row row0+k ----
    int isrc = (row0 + (lane & 7) - n) & 63;
    float sv, cv;
    sincosf(((float)isrc + 0.5f) * (2.0f * PI_F / RES), &sv, &cv);

    // ---- radii for this lane's two columns j = 2L, 2L+1 (registers) ----
    const float lm = logf(maxR);
    float ra_ = expf(((2.0f * lane + 0.5f) * (1.0f / RES)) * lm);   // maxR^normGrid
    float rb_ = expf(((2.0f * lane + 1.5f) * (1.0f / RES)) * lm);
    const float sR = (maxR * (2.0f / 1500.0f)) / (maxR - 1.0f) * 128.0f;
    const float2 r2a = make_float2((ra_ - 1.0f) * sR, (ra_ - 1.0f) * sR);
    const float2 r2b = make_float2((rb_ - 1.0f) * sR, (rb_ - 1.0f) * sR);

    // ---- publish per-warp tile ----
    s_tile[wid][lane]      = p0 * (1.0f / 255.0f);
    s_tile[wid][lane + 32] = p1 * (1.0f / 255.0f);
    __syncwarp();

    const float* __restrict__ tw = s_tile[wid];
    const float2 cc   = make_float2(cxr, cyr);
    const float2 mg   = make_float2(MAGIC, MAGIC);
    const float2 mn   = make_float2(-8388608.0f, -8388608.0f);
    const float2 neg1 = make_float2(-1.0f, -1.0f);
    float2* __restrict__ ob =
        reinterpret_cast<float2*>(out + (size_t)b * (RES * RES) + row0 * RES) + lane;

    #pragma unroll
    for (int k = 0; k < 8; k++) {
        float2 cs;
        cs.x = __shfl_sync(0xffffffffu, cv, k);   // uniform broadcast
        cs.y = __shfl_sync(0xffffffffu, sv, k);

        float va, vb;
        #define PIXEL(RR, OUTF)                                              \
        {                                                                    \
            float2 p = fma2(RR, cs, cc);          /* (ix, iy) */             \
            float2 t = add2(p, mg);               /* 2^23 + floor(p) */      \
            float2 f = add2(t, mn);               /* floor as float */       \
            float2 w = fma2(f, neg1, p);          /* frac, in [0,1] */       \
            unsigned xb = __float_as_uint(t.x);                              \
            unsigned yb = __float_as_uint(t.y);                              \
            int idx = (int)(((yb & 7u) << 3) | (xb & 7u));                   \
            const float* q = tw + idx;                                       \
            float v00 = q[0], v01 = q[1], v10 = q[8], v11 = q[9];            \
            float top = fmaf(w.x, v01 - v00, v00);                           \
            float bot = fmaf(w.x, v11 - v10, v10);                           \
            OUTF = fmaf(w.y, bot - top, top);                                \
        }
        PIXEL(r2a, va)
        PIXEL(r2b, vb)
        #undef PIXEL

        ob[k * 32] = make_float2(va, vb);   // coalesced 256B row per warp
    }
}

extern "C" void kernel_launch(void* const* d_in, const int* in_sizes, int n_in,
                              void* d_out, int out_size)
{
    const float* img      = (const float*)d_in[0];
    const float* kpLoc    = (const float*)d_in[1];
    const float* scaling  = (const float*)d_in[2];
    const float* rotation = (const float*)d_in[3];
    float* out = (float*)d_out;

    int B = out_size / (RES * RES);       // 2048
    logpolar_kernel<<<B * 2, 128>>>(img, kpLoc, scaling, rotation, out);
}

// round 9
// speedup vs baseline: 1.0194x; 1.0194x over previous
#include <cuda_runtime.h>
#include <math.h>

// Log-polar patch extraction — 8 warps per batch, warp-autonomous, quad LUT.
//   img:      [B,1,256,256] f32   (d_in[0])
//   kpLoc:    [B,2]         f32   (d_in[1])
//   scaling:  [B]           f32   (d_in[2])
//   rotation: [B]           f32   (d_in[3])
//   out:      [B,1,64,64]   f32
//
// Geometry: kpLoc in [-0.6,0.6], scaling in [0.5,2.0] => pixel-space sample
// radius r128 <= 2.05; all bilinear footprints fall inside the 8x8 window
// [floor(c)-3, floor(c)+4]^2, strictly interior to the 256x256 image.
//
// Each warp owns 8 output rows of one batch (16384 warps). Lane L owns
// radii j = 2L, 2L+1 (registers). Per-warp smem holds a 7x7 table of float4
// "quads" (the 2x2 bilinear footprint of each cell, pre-scaled by 1/255) so
// each pixel needs exactly ONE LDS.128, plus an 8-entry (cos,sin) table of
// the source angles (roll folded before trig) read as uniform LDS.64.
// Floor/index via the magic-float trick (2^23 - 0.5): fixed-latency only.

#define RES 64
#define IMG_W 256
#define PI_F 3.14159265358979323846f
#define MAGIC (8388608.0f - 0.5f)     // 2^23 - 0.5 : RNE(p + MAGIC) == 2^23 + floor(p)

__device__ __forceinline__ float2 fma2(float2 a, float2 b, float2 c) {
    float2 d;
    asm("fma.rn.f32x2 %0, %1, %2, %3;"
        : "=l"(reinterpret_cast<unsigned long long&>(d))
        : "l"(reinterpret_cast<unsigned long long&>(a)),
          "l"(reinterpret_cast<unsigned long long&>(b)),
          "l"(reinterpret_cast<unsigned long long&>(c)));
    return d;
}
__device__ __forceinline__ float2 add2(float2 a, float2 b) {
    float2 d;
    asm("add.rn.f32x2 %0, %1, %2;"
        : "=l"(reinterpret_cast<unsigned long long&>(d))
        : "l"(reinterpret_cast<unsigned long long&>(a)),
          "l"(reinterpret_cast<unsigned long long&>(b)));
    return d;
}

__global__ void __launch_bounds__(128)
logpolar_kernel(const float* __restrict__ img,
                const float* __restrict__ kpLoc,
                const float* __restrict__ scaling,
                const float* __restrict__ rotation,
                float* __restrict__ out)
{
    const int wid  = threadIdx.x >> 5;
    const int lane = threadIdx.x & 31;
    const int b    = blockIdx.x >> 1;                       // 2 blocks per batch
    const int row0 = (((blockIdx.x & 1) << 2) | wid) << 3;  // this warp's 8 rows

    __shared__ float4 s_quad[4][49];   // per-warp 7x7 quad table (x1/255)
    __shared__ float2 s_cs[4][8];      // per-warp source-angle (cos,sin)

    // Per-batch scalars (same address across warp -> broadcast LDG, L1-hot)
    const float rot = rotation[b];
    const float scl = scaling[b];
    const float kx  = kpLoc[2 * b + 0];
    const float ky  = kpLoc[2 * b + 1];
    const float maxR = 6.0f * scl;

    // Sample-grid center in pixel coords; 8x8 window origin
    const float cx = kx * 128.0f + 127.5f;
    const float cy = ky * 128.0f + 127.5f;
    const float fx0 = floorf(cx);
    const float fy0 = floorf(cy);
    const int   x0  = (int)fx0 - 3;
    const int   y0  = (int)fy0 - 3;
    const float cxr = (cx - fx0) + 3.0f;   // window-relative center, in [3,4)
    const float cyr = (cy - fy0) + 3.0f;

    // ---- build the quad table straight from global (L1-hot: 8 warps share it) ----
    const float* __restrict__ im = img + (size_t)b * (IMG_W * IMG_W);
    #pragma unroll 2
    for (int t = lane; t < 49; t += 32) {
        int qy = t / 7, qx = t - qy * 7;
        const float* p = im + (y0 + qy) * IMG_W + x0 + qx;
        float4 q;
        q.x = __ldg(p)             * (1.0f / 255.0f);
        q.y = __ldg(p + 1)         * (1.0f / 255.0f);
        q.z = __ldg(p + IMG_W)     * (1.0f / 255.0f);
        q.w = __ldg(p + IMG_W + 1) * (1.0f / 255.0f);
        s_quad[wid][t] = q;
    }

    // ---- roll amount (banker's rounding to match jnp.round) ----
    int n = (int)rintf(rot * 57.29577951308232f * (1.0f / 5.625f));
    n = ((n % RES) + RES) % RES;

    // ---- source-angle table: lane k<8 computes (cos,sin) of row row0+k ----
    int isrc = (row0 + (lane & 7) - n) & 63;
    float sv, cv;
    sincosf(((float)isrc + 0.5f) * (2.0f * PI_F / RES), &sv, &cv);
    if (lane < 8) s_cs[wid][lane] = make_float2(cv, sv);

    // ---- radii for this lane's two columns j = 2L, 2L+1 (registers) ----
    const float lm = logf(maxR);
    float ra_ = expf(((2.0f * lane + 0.5f) * (1.0f / RES)) * lm);   // maxR^normGrid
    float rb_ = expf(((2.0f * lane + 1.5f) * (1.0f / RES)) * lm);
    const float sR = (maxR * (2.0f / 1500.0f)) / (maxR - 1.0f) * 128.0f;
    const float2 r2a = make_float2((ra_ - 1.0f) * sR, (ra_ - 1.0f) * sR);
    const float2 r2b = make_float2((rb_ - 1.0f) * sR, (rb_ - 1.0f) * sR);

    __syncwarp();

    const float4* __restrict__ qw = s_quad[wid];
    const float2* __restrict__ cw = s_cs[wid];
    const float2 cc   = make_float2(cxr, cyr);
    const float2 mg   = make_float2(MAGIC, MAGIC);
    const float2 mn   = make_float2(-8388608.0f, -8388608.0f);
    const float2 neg1 = make_float2(-1.0f, -1.0f);
    float2* __restrict__ ob =
        reinterpret_cast<float2*>(out + (size_t)b * (RES * RES) + row0 * RES) + lane;

    #pragma unroll
    for (int k = 0; k < 8; k++) {
        float2 cs = cw[k];                    // uniform LDS.64 broadcast

        float va, vb;
        #define PIXEL(RR, OUTF)                                              \
        {                                                                    \
            float2 p = fma2(RR, cs, cc);          /* (ix, iy) */             \
            float2 t = add2(p, mg);               /* 2^23 + floor(p) */      \
            float2 f = add2(t, mn);               /* floor as float */       \
            float2 w = fma2(f, neg1, p);          /* frac, in [0,1] */       \
            int xi = (int)(__float_as_uint(t.x) & 7u);                       \
            int yi = (int)(__float_as_uint(t.y) & 7u);                       \
            float4 q = qw[yi * 7 + xi];           /* ONE LDS.128 */          \
            float top = fmaf(w.x, q.y - q.x, q.x);                           \
            float bot = fmaf(w.x, q.w - q.z, q.z);                           \
            OUTF = fmaf(w.y, bot - top, top);                                \
        }
        PIXEL(r2a, va)
        PIXEL(r2b, vb)
        #undef PIXEL

        ob[k * 32] = make_float2(va, vb);     // coalesced 256B row per warp
    }
}

extern "C" void kernel_launch(void* const* d_in, const int* in_sizes, int n_in,
                              void* d_out, int out_size)
{
    const float* img      = (const float*)d_in[0];
    const float* kpLoc    = (const float*)d_in[1];
    const float* scaling  = (const float*)d_in[2];
    const float* rotation = (const float*)d_in[3];
    float* out = (float*)d_out;

    int B = out_size / (RES * RES);       // 2048
    logpolar_kernel<<<B * 2, 128>>>(img, kpLoc, scaling, rotation, out);
}

// round 10
// speedup vs baseline: 1.0776x; 1.0571x over previous
#include <cuda_runtime.h>
#include <math.h>

// Log-polar patch extraction — 8 warps per batch, warp-autonomous, pair-tile.
//   img:      [B,1,256,256] f32   (d_in[0])
//   kpLoc:    [B,2]         f32   (d_in[1])
//   scaling:  [B]           f32   (d_in[2])
//   rotation: [B]           f32   (d_in[3])
//   out:      [B,1,64,64]   f32
//
// Geometry: kpLoc in [-0.6,0.6], scaling in [0.5,2.0] => pixel-space sample
// radius r128 <= 2.05; all bilinear footprints fall inside the 8x8 window
// [floor(c)-3, floor(c)+4]^2, strictly interior to the 256x256 image.
//
// Each warp owns 8 output rows of one batch (16384 warps). Lane L owns
// radii j = 2L, 2L+1 (registers). Per-warp smem:
//   s_pair[y*8+x] = (v(y,x), v(y,x+1)) / 255   -> each pixel = 2 LDS.64
//   s_cs[k]       = (cos,sin) of source angle of row row0+k (roll folded)
// Floor/index via magic-float (2^23 - 0.5): fixed-latency ops only.

#define RES 64
#define IMG_W 256
#define PI_F 3.14159265358979323846f
#define MAGIC (8388608.0f - 0.5f)     // 2^23 - 0.5 : RNE(p + MAGIC) == 2^23 + floor(p)

__device__ __forceinline__ float2 fma2(float2 a, float2 b, float2 c) {
    float2 d;
    asm("fma.rn.f32x2 %0, %1, %2, %3;"
        : "=l"(reinterpret_cast<unsigned long long&>(d))
        : "l"(reinterpret_cast<unsigned long long&>(a)),
          "l"(reinterpret_cast<unsigned long long&>(b)),
          "l"(reinterpret_cast<unsigned long long&>(c)));
    return d;
}
__device__ __forceinline__ float2 add2(float2 a, float2 b) {
    float2 d;
    asm("add.rn.f32x2 %0, %1, %2;"
        : "=l"(reinterpret_cast<unsigned long long&>(d))
        : "l"(reinterpret_cast<unsigned long long&>(a)),
          "l"(reinterpret_cast<unsigned long long&>(b)));
    return d;
}

__global__ void __launch_bounds__(128)
logpolar_kernel(const float* __restrict__ img,
                const float* __restrict__ kpLoc,
                const float* __restrict__ scaling,
                const float* __restrict__ rotation,
                float* __restrict__ out)
{
    const int wid  = threadIdx.x >> 5;
    const int lane = threadIdx.x & 31;
    const int b    = blockIdx.x >> 1;                       // 2 blocks per batch
    const int row0 = (((blockIdx.x & 1) << 2) | wid) << 3;  // this warp's 8 rows

    __shared__ float2 s_pair[4][64];   // per-warp: (v(y,x), v(y,x+1)) / 255
    __shared__ float2 s_cs[4][8];      // per-warp source-angle (cos,sin)

    // Per-batch scalars (same address across warp -> broadcast LDG, L1-hot)
    const float rot = rotation[b];
    const float scl = scaling[b];
    const float kx  = kpLoc[2 * b + 0];
    const float ky  = kpLoc[2 * b + 1];
    const float maxR = 6.0f * scl;

    // Sample-grid center in pixel coords; 8x8 window origin
    const float cx = kx * 128.0f + 127.5f;
    const float cy = ky * 128.0f + 127.5f;
    const float fx0 = floorf(cx);
    const float fy0 = floorf(cy);
    const int   x0  = (int)fx0 - 3;
    const int   y0  = (int)fy0 - 3;
    const float cxr = (cx - fx0) + 3.0f;   // window-relative center, in [3,4)
    const float cyr = (cy - fy0) + 3.0f;

    // ---- tile loads first (latency overlapped by MUFU work below) ----
    // lane handles cells t = lane and lane+32; cell t: y=t>>3, x=t&7.
    // pair needs v(y,x) and v(y,x+1); x0+8 <= 212 stays interior.
    const float* __restrict__ im = img + (size_t)b * (IMG_W * IMG_W);
    const float* pA = im + (y0 + (lane >> 3)) * IMG_W + x0 + (lane & 7);
    const float* pB = im + (y0 + 4 + (lane >> 3)) * IMG_W + x0 + (lane & 7);
    float a0 = __ldg(pA), a1 = __ldg(pA + 1);
    float b0 = __ldg(pB), b1 = __ldg(pB + 1);

    // ---- roll amount (banker's rounding to match jnp.round) ----
    int n = (int)rintf(rot * 57.29577951308232f * (1.0f / 5.625f));
    n = ((n % RES) + RES) % RES;

    // ---- source-angle table: lane k<8 computes (cos,sin) of row row0+k ----
    int isrc = (row0 + (lane & 7) - n) & 63;
    float sv, cv;
    sincosf(((float)isrc + 0.5f) * (2.0f * PI_F / RES), &sv, &cv);
    if (lane < 8) s_cs[wid][lane] = make_float2(cv, sv);

    // ---- radii for this lane's two columns j = 2L, 2L+1 (registers) ----
    const float lm = logf(maxR);
    float ra_ = expf(((2.0f * lane + 0.5f) * (1.0f / RES)) * lm);   // maxR^normGrid
    float rb_ = expf(((2.0f * lane + 1.5f) * (1.0f / RES)) * lm);
    const float sR = (maxR * (2.0f / 1500.0f)) / (maxR - 1.0f) * 128.0f;
    const float2 r2a = make_float2((ra_ - 1.0f) * sR, (ra_ - 1.0f) * sR);
    const float2 r2b = make_float2((rb_ - 1.0f) * sR, (rb_ - 1.0f) * sR);

    // ---- publish per-warp pair tile ----
    s_pair[wid][lane]      = make_float2(a0 * (1.0f / 255.0f), a1 * (1.0f / 255.0f));
    s_pair[wid][lane + 32] = make_float2(b0 * (1.0f / 255.0f), b1 * (1.0f / 255.0f));
    __syncwarp();

    const float2* __restrict__ tw = s_pair[wid];
    const float2* __restrict__ cw = s_cs[wid];
    const float2 cc   = make_float2(cxr, cyr);
    const float2 mg   = make_float2(MAGIC, MAGIC);
    const float2 mn   = make_float2(-8388608.0f, -8388608.0f);
    const float2 neg1 = make_float2(-1.0f, -1.0f);
    float2* __restrict__ ob =
        reinterpret_cast<float2*>(out + (size_t)b * (RES * RES) + row0 * RES) + lane;

    #pragma unroll
    for (int k = 0; k < 8; k++) {
        float2 cs = cw[k];                    // uniform LDS.64 broadcast

        float va, vb;
        #define PIXEL(RR, OUTF)                                              \
        {                                                                    \
            float2 p = fma2(RR, cs, cc);          /* (ix, iy) */             \
            float2 t = add2(p, mg);               /* 2^23 + floor(p) */      \
            float2 f = add2(t, mn);               /* floor as float */       \
            float2 w = fma2(f, neg1, p);          /* frac, in [0,1] */       \
            int idx = (int)((( __float_as_uint(t.y) & 7u) << 3)              \
                            | (__float_as_uint(t.x) & 7u));                  \
            float2 qt = tw[idx];                  /* v00, v01 (LDS.64) */    \
            float2 qb = tw[idx + 8];              /* v10, v11 (LDS.64) */    \
            float top = fmaf(w.x, qt.y - qt.x, qt.x);                        \
            float bot = fmaf(w.x, qb.y - qb.x, qb.x);                        \
            OUTF = fmaf(w.y, bot - top, top);                                \
        }
        PIXEL(r2a, va)
        PIXEL(r2b, vb)
        #undef PIXEL

        ob[k * 32] = make_float2(va, vb);     // coalesced 256B row per warp
    }
}

extern "C" void kernel_launch(void* const* d_in, const int* in_sizes, int n_in,
                              void* d_out, int out_size)
{
    const float* img      = (const float*)d_in[0];
    const float* kpLoc    = (const float*)d_in[1];
    const float* scaling  = (const float*)d_in[2];
    const float* rotation = (const float*)d_in[3];
    float* out = (float*)d_out;

    int B = out_size / (RES * RES);       // 2048
    logpolar_kernel<<<B * 2, 128>>>(img, kpLoc, scaling, rotation, out);
}

// round 11
// speedup vs baseline: 1.1569x; 1.0735x over previous
#include <cuda_runtime.h>
#include <math.h>

// Log-polar patch extraction — 8 warps per batch, warp-autonomous, pair-tile.
//   img:      [B,1,256,256] f32   (d_in[0])
//   kpLoc:    [B,2]         f32   (d_in[1])
//   scaling:  [B]           f32   (d_in[2])
//   rotation: [B]           f32   (d_in[3])
//   out:      [B,1,64,64]   f32
//
// Geometry: kpLoc in [-0.6,0.6], scaling in [0.5,2.0] => pixel-space sample
// radius r128 <= 2.05; all bilinear footprints fall inside the 8x8 window
// [floor(c)-3, floor(c)+4]^2, strictly interior to the 256x256 image.
//
// Per-warp smem:
//   s_pair[y*8+x] = (v(y,x), v(y,x+1)-v(y,x)) / 255  -> tap-row lerp = 1 FFMA
//   s_cs[k]       = (cos,sin) of source angle of row row0+k (roll folded)
// Transcendentals use fast MUFU intrinsics (__sincosf/__expf/__logf):
// ~2^-21 rel error vs 1e-3 budget. Floor/index via magic-float (2^23-0.5);
// since mantissa(2^23+v)=v and 0x4B000000*9 = 0 mod 64, the cell index is
// (yb*8+xb)&63 — one IMAD + one LOP3.

#define RES 64
#define IMG_W 256
#define PI_F 3.14159265358979323846f
#define MAGIC (8388608.0f - 0.5f)     // 2^23 - 0.5 : RNE(p + MAGIC) == 2^23 + floor(p)

__device__ __forceinline__ float2 fma2(float2 a, float2 b, float2 c) {
    float2 d;
    asm("fma.rn.f32x2 %0, %1, %2, %3;"
        : "=l"(reinterpret_cast<unsigned long long&>(d))
        : "l"(reinterpret_cast<unsigned long long&>(a)),
          "l"(reinterpret_cast<unsigned long long&>(b)),
          "l"(reinterpret_cast<unsigned long long&>(c)));
    return d;
}
__device__ __forceinline__ float2 add2(float2 a, float2 b) {
    float2 d;
    asm("add.rn.f32x2 %0, %1, %2;"
        : "=l"(reinterpret_cast<unsigned long long&>(d))
        : "l"(reinterpret_cast<unsigned long long&>(a)),
          "l"(reinterpret_cast<unsigned long long&>(b)));
    return d;
}

__global__ void __launch_bounds__(128)
logpolar_kernel(const float* __restrict__ img,
                const float* __restrict__ kpLoc,
                const float* __restrict__ scaling,
                const float* __restrict__ rotation,
                float* __restrict__ out)
{
    const int wid  = threadIdx.x >> 5;
    const int lane = threadIdx.x & 31;
    const int b    = blockIdx.x >> 1;                       // 2 blocks per batch
    const int row0 = (((blockIdx.x & 1) << 2) | wid) << 3;  // this warp's 8 rows

    __shared__ float2 s_pair[4][64];   // per-warp: (v, v_right - v) / 255
    __shared__ float2 s_cs[4][8];      // per-warp source-angle (cos,sin)

    // Per-batch scalars (same address across warp -> broadcast LDG, L1-hot)
    const float rot = rotation[b];
    const float scl = scaling[b];
    const float kx  = kpLoc[2 * b + 0];
    const float ky  = kpLoc[2 * b + 1];
    const float maxR = 6.0f * scl;

    // Sample-grid center in pixel coords; 8x8 window origin
    const float cx = kx * 128.0f + 127.5f;
    const float cy = ky * 128.0f + 127.5f;
    const float fx0 = floorf(cx);
    const float fy0 = floorf(cy);
    const int   x0  = (int)fx0 - 3;
    const int   y0  = (int)fy0 - 3;
    const float cxr = (cx - fx0) + 3.0f;   // window-relative center, in [3,4)
    const float cyr = (cy - fy0) + 3.0f;

    // ---- tile loads first (latency overlapped by MUFU work below) ----
    const float* __restrict__ im = img + (size_t)b * (IMG_W * IMG_W);
    const float* pA = im + (y0 + (lane >> 3)) * IMG_W + x0 + (lane & 7);
    const float* pB = im + (y0 + 4 + (lane >> 3)) * IMG_W + x0 + (lane & 7);
    float a0 = __ldg(pA), a1 = __ldg(pA + 1);
    float b0 = __ldg(pB), b1 = __ldg(pB + 1);

    // ---- roll amount (exact arithmetic + rintf; matches jnp.round) ----
    int n = (int)rintf(rot * 57.29577951308232f * (1.0f / 5.625f));
    n = ((n % RES) + RES) % RES;

    // ---- source-angle table: lane k<8 computes (cos,sin) of row row0+k ----
    int isrc = (row0 + (lane & 7) - n) & 63;
    float sv, cv;
    __sincosf(((float)isrc + 0.5f) * (2.0f * PI_F / RES), &sv, &cv);
    if (lane < 8) s_cs[wid][lane] = make_float2(cv, sv);

    // ---- radii for this lane's two columns j = 2L, 2L+1 (registers) ----
    const float lm = __logf(maxR);
    float ra_ = __expf(((2.0f * lane + 0.5f) * (1.0f / RES)) * lm);   // maxR^normGrid
    float rb_ = __expf(((2.0f * lane + 1.5f) * (1.0f / RES)) * lm);
    const float sR = (maxR * (2.0f / 1500.0f)) / (maxR - 1.0f) * 128.0f;
    const float2 r2a = make_float2((ra_ - 1.0f) * sR, (ra_ - 1.0f) * sR);
    const float2 r2b = make_float2((rb_ - 1.0f) * sR, (rb_ - 1.0f) * sR);

    // ---- publish per-warp pair tile: (v00, v01 - v00) scaled by 1/255 ----
    s_pair[wid][lane]      = make_float2(a0 * (1.0f / 255.0f), (a1 - a0) * (1.0f / 255.0f));
    s_pair[wid][lane + 32] = make_float2(b0 * (1.0f / 255.0f), (b1 - b0) * (1.0f / 255.0f));
    __syncwarp();

    const float2* __restrict__ tw = s_pair[wid];
    const float2* __restrict__ cw = s_cs[wid];
    const float2 cc   = make_float2(cxr, cyr);
    const float2 mg   = make_float2(MAGIC, MAGIC);
    const float2 mn   = make_float2(-8388608.0f, -8388608.0f);
    const float2 neg1 = make_float2(-1.0f, -1.0f);
    float2* __restrict__ ob =
        reinterpret_cast<float2*>(out + (size_t)b * (RES * RES) + row0 * RES) + lane;

    #pragma unroll
    for (int k = 0; k < 8; k++) {
        float2 cs = cw[k];                    // uniform LDS.64 broadcast

        float va, vb;
        #define PIXEL(RR, OUTF)                                              \
        {                                                                    \
            float2 p = fma2(RR, cs, cc);          /* (ix, iy) */             \
            float2 t = add2(p, mg);               /* 2^23 + floor(p) */      \
            float2 f = add2(t, mn);               /* floor as float */       \
            float2 w = fma2(f, neg1, p);          /* frac, in [0,1] */       \
            unsigned xb = __float_as_uint(t.x);                              \
            unsigned yb = __float_as_uint(t.y);                              \
            int idx = (int)((yb * 8u + xb) & 63u);  /* IMAD + LOP3 */        \
            float2 qt = tw[idx];                  /* (v00, v01-v00) */       \
            float2 qb = tw[idx + 8];              /* (v10, v11-v10) */       \
            float top = fmaf(w.x, qt.y, qt.x);                               \
            float bot = fmaf(w.x, qb.y, qb.x);                               \
            OUTF = fmaf(w.y, bot - top, top);                                \
        }
        PIXEL(r2a, va)
        PIXEL(r2b, vb)
        #undef PIXEL

        ob[k * 32] = make_float2(va, vb);     // coalesced 256B row per warp
    }
}

extern "C" void kernel_launch(void* const* d_in, const int* in_sizes, int n_in,
                              void* d_out, int out_size)
{
    const float* img      = (const float*)d_in[0];
    const float* kpLoc    = (const float*)d_in[1];
    const float* scaling  = (const float*)d_in[2];
    const float* rotation = (const float*)d_in[3];
    float* out = (float*)d_out;

    int B = out_size / (RES * RES);       // 2048
    logpolar_kernel<<<B * 2, 128>>>(img, kpLoc, scaling, rotation, out);
}